// round 1
// baseline (speedup 1.0000x reference)
#include <cuda_runtime.h>
#include <stdint.h>

// Problem constants (fixed by the dataset).
#define SRC_SIZE 262144
#define DST_SIZE 65536
#define N_EDGES  2097152
#define BATCH    4
#define FEAT     32

// ---------------------------------------------------------------------------
// Scratch (device globals; no allocation allowed in kernel_launch).
// ---------------------------------------------------------------------------
__device__ float g_norm[DST_SIZE];          // sum of weights per dst
__device__ int   g_counts[DST_SIZE];        // edges per dst
__device__ int   g_offsets[DST_SIZE + 1];   // exclusive prefix sum
__device__ int   g_cursor[DST_SIZE];        // scatter cursors
__device__ int   g_sorted_src[N_EDGES];     // src index, dst-sorted
__device__ float g_sorted_w[N_EDGES];       // normalized weight, dst-sorted

// ---------------------------------------------------------------------------
// K1: zero norm + counts
// ---------------------------------------------------------------------------
__global__ void k_zero() {
    int i = blockIdx.x * blockDim.x + threadIdx.x;
    if (i < DST_SIZE) {
        g_norm[i] = 0.0f;
        g_counts[i] = 0;
    }
}

// ---------------------------------------------------------------------------
// K2: histogram + weight-sum per dst
// ---------------------------------------------------------------------------
__global__ void k_hist(const float* __restrict__ weights,
                       const int* __restrict__ dst_idx, int n_edges) {
    int e = blockIdx.x * blockDim.x + threadIdx.x;
    if (e < n_edges) {
        int d = dst_idx[e];
        atomicAdd(&g_counts[d], 1);
        atomicAdd(&g_norm[d], weights[e]);
    }
}

// ---------------------------------------------------------------------------
// K3: exclusive scan of g_counts[65536] with one 1024-thread block.
// Each thread owns 64 contiguous counters.
// ---------------------------------------------------------------------------
__global__ void k_scan() {
    const int t = threadIdx.x;           // 0..1023
    const int base = t * 64;

    // Local sum over this thread's 64 counters.
    int s = 0;
#pragma unroll 8
    for (int i = 0; i < 64; i++) s += g_counts[base + i];

    // Block-wide exclusive scan of the 1024 per-thread sums.
    const int lane = t & 31;
    const int warp = t >> 5;
    int v = s;
#pragma unroll
    for (int off = 1; off < 32; off <<= 1) {
        int n = __shfl_up_sync(0xFFFFFFFFu, v, off);
        if (lane >= off) v += n;
    }
    __shared__ int wsum[32];
    if (lane == 31) wsum[warp] = v;
    __syncthreads();
    if (warp == 0) {
        int u = (lane < 32) ? wsum[lane] : 0;
#pragma unroll
        for (int off = 1; off < 32; off <<= 1) {
            int n = __shfl_up_sync(0xFFFFFFFFu, u, off);
            if (lane >= off) u += n;
        }
        wsum[lane] = u;  // inclusive scan of warp sums
    }
    __syncthreads();

    int excl = v - s + ((warp > 0) ? wsum[warp - 1] : 0);

    // Emit per-counter exclusive offsets + init cursors.
    int run = excl;
#pragma unroll 8
    for (int i = 0; i < 64; i++) {
        int c = g_counts[base + i];
        g_offsets[base + i] = run;
        g_cursor[base + i] = run;
        run += c;
    }
    if (t == 1023) g_offsets[DST_SIZE] = run;
}

// ---------------------------------------------------------------------------
// K4: scatter edges into dst-sorted order; store normalized weights.
// ---------------------------------------------------------------------------
__global__ void k_scatter(const float* __restrict__ weights,
                          const int* __restrict__ src_idx,
                          const int* __restrict__ dst_idx, int n_edges) {
    int e = blockIdx.x * blockDim.x + threadIdx.x;
    if (e < n_edges) {
        int d = dst_idx[e];
        int pos = atomicAdd(&g_cursor[d], 1);
        float nm = g_norm[d];
        g_sorted_src[pos] = src_idx[e];
        g_sorted_w[pos]   = weights[e] / (nm + 1e-8f);
    }
}

// ---------------------------------------------------------------------------
// K5: atomic-free segmented reduction. One warp per dst node.
// Lane layout: b = lane>>3 (4 batches), fg = lane&7 (8 float4 groups of FEAT=32).
// ---------------------------------------------------------------------------
__global__ void __launch_bounds__(256)
k_reduce(const float* __restrict__ x, float* __restrict__ out) {
    const int warp_global = (blockIdx.x * blockDim.x + threadIdx.x) >> 5;
    if (warp_global >= DST_SIZE) return;
    const int lane = threadIdx.x & 31;
    const int b  = lane >> 3;
    const int fg = lane & 7;

    const int beg = g_offsets[warp_global];
    const int end = g_offsets[warp_global + 1];

    const float* xb = x + (size_t)b * (SRC_SIZE * FEAT) + fg * 4;

    float ax = 0.f, ay = 0.f, az = 0.f, aw = 0.f;

    int j = beg;
    // Unroll-2: two independent gathers in flight per lane.
    for (; j + 1 < end; j += 2) {
        int   s0 = g_sorted_src[j];
        int   s1 = g_sorted_src[j + 1];
        float w0 = g_sorted_w[j];
        float w1 = g_sorted_w[j + 1];
        float4 v0 = *(const float4*)(xb + (size_t)s0 * FEAT);
        float4 v1 = *(const float4*)(xb + (size_t)s1 * FEAT);
        ax += w0 * v0.x; ay += w0 * v0.y; az += w0 * v0.z; aw += w0 * v0.w;
        ax += w1 * v1.x; ay += w1 * v1.y; az += w1 * v1.z; aw += w1 * v1.w;
    }
    if (j < end) {
        int   s0 = g_sorted_src[j];
        float w0 = g_sorted_w[j];
        float4 v0 = *(const float4*)(xb + (size_t)s0 * FEAT);
        ax += w0 * v0.x; ay += w0 * v0.y; az += w0 * v0.z; aw += w0 * v0.w;
    }

    float4 r = make_float4(ax, ay, az, aw);
    float* o = out + (size_t)b * (DST_SIZE * FEAT) + (size_t)warp_global * FEAT + fg * 4;
    *(float4*)o = r;
}

// ---------------------------------------------------------------------------
// kernel_launch
// Inputs (metadata order): x [B,SRC,F] f32, weights [E] f32,
//                          src_idx [E] i32, dst_idx [E] i32.
// Output: [B, DST, F] f32.
// ---------------------------------------------------------------------------
extern "C" void kernel_launch(void* const* d_in, const int* in_sizes, int n_in,
                              void* d_out, int out_size) {
    const float* x       = (const float*)d_in[0];
    const float* weights = (const float*)d_in[1];
    const int*   src_idx = (const int*)d_in[2];
    const int*   dst_idx = (const int*)d_in[3];
    float*       out     = (float*)d_out;
    const int n_edges = in_sizes[1];

    // K1: zero scratch
    k_zero<<<(DST_SIZE + 255) / 256, 256>>>();
    // K2: histogram + norm
    k_hist<<<(n_edges + 255) / 256, 256>>>(weights, dst_idx, n_edges);
    // K3: prefix scan
    k_scan<<<1, 1024>>>();
    // K4: bin edges by dst
    k_scatter<<<(n_edges + 255) / 256, 256>>>(weights, src_idx, dst_idx, n_edges);
    // K5: segmented reduce, one warp per dst (65536 warps, 8 warps/block)
    k_reduce<<<DST_SIZE / 8, 256>>>(x, out);
}

// round 2
// speedup vs baseline: 1.8413x; 1.8413x over previous
#include <cuda_runtime.h>
#include <stdint.h>

#define SRC_SIZE 262144
#define DST_SIZE 65536
#define N_EDGES  2097152
#define BATCH    4
#define FEAT     32

#define SCAN_BLOCKS 256
#define SCAN_CHUNK  256   // DST_SIZE / SCAN_BLOCKS

// ---------------------------------------------------------------------------
// Scratch
// ---------------------------------------------------------------------------
__device__ float g_norm[DST_SIZE];
__device__ float g_inv[DST_SIZE];           // 1/(norm+1e-8), computed in scan pass 3
__device__ int   g_counts[DST_SIZE];
__device__ int   g_offsets[DST_SIZE + 1];
__device__ int   g_cursor[DST_SIZE];
__device__ int   g_blocksum[SCAN_BLOCKS];
__device__ int   g_blockoff[SCAN_BLOCKS];
__device__ int2  g_sorted[N_EDGES];         // {src, __float_as_int(w)}

// ---------------------------------------------------------------------------
// K1: zero norm + counts
// ---------------------------------------------------------------------------
__global__ void k_zero() {
    int i = blockIdx.x * blockDim.x + threadIdx.x;
    if (i < DST_SIZE) {
        g_norm[i] = 0.0f;
        g_counts[i] = 0;
    }
}

// ---------------------------------------------------------------------------
// K2: histogram + weight-sum per dst
// ---------------------------------------------------------------------------
__global__ void k_hist(const float* __restrict__ weights,
                       const int* __restrict__ dst_idx, int n_edges) {
    int e = blockIdx.x * blockDim.x + threadIdx.x;
    if (e < n_edges) {
        int d = __ldg(&dst_idx[e]);
        atomicAdd(&g_counts[d], 1);
        atomicAdd(&g_norm[d], __ldg(&weights[e]));
    }
}

// ---------------------------------------------------------------------------
// Block-wide inclusive scan helper (256 threads = 8 warps)
// ---------------------------------------------------------------------------
__device__ __forceinline__ int block_scan_incl(int v, int* sh) {
    const int lane = threadIdx.x & 31;
    const int warp = threadIdx.x >> 5;
#pragma unroll
    for (int off = 1; off < 32; off <<= 1) {
        int n = __shfl_up_sync(0xFFFFFFFFu, v, off);
        if (lane >= off) v += n;
    }
    if (lane == 31) sh[warp] = v;
    __syncthreads();
    if (warp == 0) {
        int u = (lane < 8) ? sh[lane] : 0;
#pragma unroll
        for (int off = 1; off < 8; off <<= 1) {
            int n = __shfl_up_sync(0xFFFFFFFFu, u, off);
            if (lane >= off) u += n;
        }
        if (lane < 8) sh[lane] = u;
    }
    __syncthreads();
    if (warp > 0) v += sh[warp - 1];
    return v;
}

// ---------------------------------------------------------------------------
// K3a: per-block sums of counts (256 blocks x 256 counters)
// ---------------------------------------------------------------------------
__global__ void k_scan_a() {
    __shared__ int sh[8];
    const int d = blockIdx.x * SCAN_CHUNK + threadIdx.x;
    int c = g_counts[d];
    // warp reduce
    const int lane = threadIdx.x & 31;
    const int warp = threadIdx.x >> 5;
    int s = c;
#pragma unroll
    for (int off = 16; off > 0; off >>= 1)
        s += __shfl_down_sync(0xFFFFFFFFu, s, off);
    if (lane == 0) sh[warp] = s;
    __syncthreads();
    if (warp == 0) {
        int u = (lane < 8) ? sh[lane] : 0;
#pragma unroll
        for (int off = 4; off > 0; off >>= 1)
            u += __shfl_down_sync(0xFFFFFFFFu, u, off);
        if (lane == 0) g_blocksum[blockIdx.x] = u;
    }
}

// ---------------------------------------------------------------------------
// K3b: exclusive scan of 256 block sums (1 block, 256 threads)
// ---------------------------------------------------------------------------
__global__ void k_scan_b() {
    __shared__ int sh[8];
    int v = g_blocksum[threadIdx.x];
    int incl = block_scan_incl(v, sh);
    g_blockoff[threadIdx.x] = incl - v;
}

// ---------------------------------------------------------------------------
// K3c: per-block rescan -> offsets + cursors; also precompute inv_norm
// ---------------------------------------------------------------------------
__global__ void k_scan_c() {
    __shared__ int sh[8];
    const int d = blockIdx.x * SCAN_CHUNK + threadIdx.x;
    int c = g_counts[d];
    int incl = block_scan_incl(c, sh);
    int off = g_blockoff[blockIdx.x] + incl - c;
    g_offsets[d] = off;
    g_cursor[d]  = off;
    g_inv[d] = 1.0f / (g_norm[d] + 1e-8f);
    if (d == DST_SIZE - 1) g_offsets[DST_SIZE] = off + c;
}

// ---------------------------------------------------------------------------
// K4: scatter edges into dst-sorted order (packed {src, w})
// ---------------------------------------------------------------------------
__global__ void k_scatter(const float* __restrict__ weights,
                          const int* __restrict__ src_idx,
                          const int* __restrict__ dst_idx, int n_edges) {
    int e = blockIdx.x * blockDim.x + threadIdx.x;
    if (e < n_edges) {
        int d = __ldg(&dst_idx[e]);
        int pos = atomicAdd(&g_cursor[d], 1);
        int2 p;
        p.x = __ldg(&src_idx[e]);
        p.y = __float_as_int(__ldg(&weights[e]));
        g_sorted[pos] = p;
    }
}

// ---------------------------------------------------------------------------
// K5: atomic-free segmented reduction. One warp per dst.
// lane: b = lane>>3 (batch), fg = lane&7 (float4 group). Unroll 4.
// ---------------------------------------------------------------------------
__global__ void __launch_bounds__(256)
k_reduce(const float* __restrict__ x, float* __restrict__ out) {
    const int dst = (blockIdx.x * blockDim.x + threadIdx.x) >> 5;
    if (dst >= DST_SIZE) return;
    const int lane = threadIdx.x & 31;
    const int b  = lane >> 3;
    const int fg = lane & 7;

    const int beg = g_offsets[dst];
    const int end = g_offsets[dst + 1];

    const float* xb = x + (size_t)b * (SRC_SIZE * FEAT) + fg * 4;

    float ax = 0.f, ay = 0.f, az = 0.f, aw = 0.f;

    int j = beg;
    for (; j + 3 < end; j += 4) {
        int2 p0 = g_sorted[j];
        int2 p1 = g_sorted[j + 1];
        int2 p2 = g_sorted[j + 2];
        int2 p3 = g_sorted[j + 3];
        float4 v0 = *(const float4*)(xb + (size_t)p0.x * FEAT);
        float4 v1 = *(const float4*)(xb + (size_t)p1.x * FEAT);
        float4 v2 = *(const float4*)(xb + (size_t)p2.x * FEAT);
        float4 v3 = *(const float4*)(xb + (size_t)p3.x * FEAT);
        float w0 = __int_as_float(p0.y), w1 = __int_as_float(p1.y);
        float w2 = __int_as_float(p2.y), w3 = __int_as_float(p3.y);
        ax += w0 * v0.x; ay += w0 * v0.y; az += w0 * v0.z; aw += w0 * v0.w;
        ax += w1 * v1.x; ay += w1 * v1.y; az += w1 * v1.z; aw += w1 * v1.w;
        ax += w2 * v2.x; ay += w2 * v2.y; az += w2 * v2.z; aw += w2 * v2.w;
        ax += w3 * v3.x; ay += w3 * v3.y; az += w3 * v3.z; aw += w3 * v3.w;
    }
    for (; j < end; j++) {
        int2 p0 = g_sorted[j];
        float4 v0 = *(const float4*)(xb + (size_t)p0.x * FEAT);
        float w0 = __int_as_float(p0.y);
        ax += w0 * v0.x; ay += w0 * v0.y; az += w0 * v0.z; aw += w0 * v0.w;
    }

    const float inv = g_inv[dst];
    float4 r = make_float4(ax * inv, ay * inv, az * inv, aw * inv);
    float* o = out + (size_t)b * (DST_SIZE * FEAT) + (size_t)dst * FEAT + fg * 4;
    *(float4*)o = r;
}

// ---------------------------------------------------------------------------
// kernel_launch
// ---------------------------------------------------------------------------
extern "C" void kernel_launch(void* const* d_in, const int* in_sizes, int n_in,
                              void* d_out, int out_size) {
    const float* x       = (const float*)d_in[0];
    const float* weights = (const float*)d_in[1];
    const int*   src_idx = (const int*)d_in[2];
    const int*   dst_idx = (const int*)d_in[3];
    float*       out     = (float*)d_out;
    const int n_edges = in_sizes[1];

    k_zero<<<(DST_SIZE + 255) / 256, 256>>>();
    k_hist<<<(n_edges + 255) / 256, 256>>>(weights, dst_idx, n_edges);
    k_scan_a<<<SCAN_BLOCKS, SCAN_CHUNK>>>();
    k_scan_b<<<1, SCAN_BLOCKS>>>();
    k_scan_c<<<SCAN_BLOCKS, SCAN_CHUNK>>>();
    k_scatter<<<(n_edges + 255) / 256, 256>>>(weights, src_idx, dst_idx, n_edges);
    k_reduce<<<DST_SIZE / 8, 256>>>(x, out);
}

// round 3
// speedup vs baseline: 1.9671x; 1.0684x over previous
#include <cuda_runtime.h>
#include <stdint.h>

#define SRC_SIZE 262144
#define DST_SIZE 65536
#define N_EDGES  2097152
#define BATCH    4
#define FEAT     32

#define SCAN_BLOCKS 256
#define SCAN_CHUNK  256   // DST_SIZE / SCAN_BLOCKS

#define FIX_SCALE 16777216.0f       // 2^24
#define INV_FIX   (1.0f / 16777216.0f)

// ---------------------------------------------------------------------------
// Scratch
// ---------------------------------------------------------------------------
__device__ unsigned long long g_hist[DST_SIZE];  // {count:u32 | fixed24(sum w):u32}
__device__ float g_inv[DST_SIZE];                // 1/(norm+1e-8)
__device__ int   g_offsets[DST_SIZE + 1];
__device__ int   g_cursor[DST_SIZE];
__device__ int   g_blocksum[SCAN_BLOCKS];
__device__ int2  g_sorted[N_EDGES];              // {src, __float_as_int(w)}

// ---------------------------------------------------------------------------
// K1: zero packed histogram
// ---------------------------------------------------------------------------
__global__ void k_zero() {
    int i = blockIdx.x * blockDim.x + threadIdx.x;
    if (i < DST_SIZE) g_hist[i] = 0ULL;
}

// ---------------------------------------------------------------------------
// K2: single packed 64-bit atomic per edge: count += 1, norm += fix24(w)
// ---------------------------------------------------------------------------
__global__ void k_hist(const float* __restrict__ weights,
                       const int* __restrict__ dst_idx, int n_edges) {
    int e = blockIdx.x * blockDim.x + threadIdx.x;
    if (e < n_edges) {
        int d = __ldg(&dst_idx[e]);
        float w = __ldg(&weights[e]);
        unsigned long long v =
            (1ULL << 32) | (unsigned long long)(unsigned int)(w * FIX_SCALE);
        atomicAdd(&g_hist[d], v);
    }
}

// ---------------------------------------------------------------------------
// K3a: per-block sums of counts (256 blocks x 256 counters)
// ---------------------------------------------------------------------------
__global__ void k_scan_a() {
    __shared__ int sh[8];
    const int d = blockIdx.x * SCAN_CHUNK + threadIdx.x;
    int c = (int)(g_hist[d] >> 32);
    const int lane = threadIdx.x & 31;
    const int warp = threadIdx.x >> 5;
    int s = c;
#pragma unroll
    for (int off = 16; off > 0; off >>= 1)
        s += __shfl_down_sync(0xFFFFFFFFu, s, off);
    if (lane == 0) sh[warp] = s;
    __syncthreads();
    if (warp == 0) {
        int u = (lane < 8) ? sh[lane] : 0;
#pragma unroll
        for (int off = 4; off > 0; off >>= 1)
            u += __shfl_down_sync(0xFFFFFFFFu, u, off);
        if (lane == 0) g_blocksum[blockIdx.x] = u;
    }
}

// ---------------------------------------------------------------------------
// K3c: per-block rescan. Each block redundantly reduces its prefix of the
// 256 block sums (replaces the old separate k_scan_b launch), then scans its
// 256 counters, emitting offsets + cursors + inv_norm.
// ---------------------------------------------------------------------------
__global__ void k_scan_c() {
    __shared__ int sh[8];
    __shared__ int sh2[8];
    __shared__ int s_prefix;

    const int t = threadIdx.x;
    const int lane = t & 31;
    const int warp = t >> 5;

    // Reduce prefix of block sums: sum g_blocksum[0 .. blockIdx.x-1]
    int p = (t < blockIdx.x) ? g_blocksum[t] : 0;
#pragma unroll
    for (int off = 16; off > 0; off >>= 1)
        p += __shfl_down_sync(0xFFFFFFFFu, p, off);
    if (lane == 0) sh2[warp] = p;
    __syncthreads();
    if (t == 0) {
        int acc = 0;
#pragma unroll
        for (int i = 0; i < 8; i++) acc += sh2[i];
        s_prefix = acc;
    }

    // Inclusive scan of this block's 256 counters.
    const int d = blockIdx.x * SCAN_CHUNK + t;
    unsigned long long h = g_hist[d];
    int c = (int)(h >> 32);
    float norm = (float)(unsigned int)(h & 0xFFFFFFFFULL) * INV_FIX;

    int v = c;
#pragma unroll
    for (int off = 1; off < 32; off <<= 1) {
        int n = __shfl_up_sync(0xFFFFFFFFu, v, off);
        if (lane >= off) v += n;
    }
    if (lane == 31) sh[warp] = v;
    __syncthreads();
    if (warp == 0) {
        int u = (lane < 8) ? sh[lane] : 0;
#pragma unroll
        for (int off = 1; off < 8; off <<= 1) {
            int n = __shfl_up_sync(0xFFFFFFFFu, u, off);
            if (lane >= off) u += n;
        }
        if (lane < 8) sh[lane] = u;
    }
    __syncthreads();
    int incl = v + ((warp > 0) ? sh[warp - 1] : 0);

    int off = s_prefix + incl - c;
    g_offsets[d] = off;
    g_cursor[d]  = off;
    g_inv[d] = 1.0f / (norm + 1e-8f);
    if (d == DST_SIZE - 1) g_offsets[DST_SIZE] = off + c;
}

// ---------------------------------------------------------------------------
// K4: scatter edges into dst-sorted order (packed {src, w})
// ---------------------------------------------------------------------------
__global__ void k_scatter(const float* __restrict__ weights,
                          const int* __restrict__ src_idx,
                          const int* __restrict__ dst_idx, int n_edges) {
    int e = blockIdx.x * blockDim.x + threadIdx.x;
    if (e < n_edges) {
        int d = __ldg(&dst_idx[e]);
        int pos = atomicAdd(&g_cursor[d], 1);
        int2 p;
        p.x = __ldg(&src_idx[e]);
        p.y = __float_as_int(__ldg(&weights[e]));
        g_sorted[pos] = p;
    }
}

// ---------------------------------------------------------------------------
// K5: atomic-free segmented reduction. One warp per dst.
// lane: b = lane>>3 (batch), fg = lane&7 (float4 group). Unroll 4.
// ---------------------------------------------------------------------------
__global__ void __launch_bounds__(256)
k_reduce(const float* __restrict__ x, float* __restrict__ out) {
    const int dst = (blockIdx.x * blockDim.x + threadIdx.x) >> 5;
    if (dst >= DST_SIZE) return;
    const int lane = threadIdx.x & 31;
    const int b  = lane >> 3;
    const int fg = lane & 7;

    const int beg = g_offsets[dst];
    const int end = g_offsets[dst + 1];

    const float* xb = x + (size_t)b * (SRC_SIZE * FEAT) + fg * 4;

    float ax = 0.f, ay = 0.f, az = 0.f, aw = 0.f;

    int j = beg;
    for (; j + 3 < end; j += 4) {
        int2 p0 = g_sorted[j];
        int2 p1 = g_sorted[j + 1];
        int2 p2 = g_sorted[j + 2];
        int2 p3 = g_sorted[j + 3];
        float4 v0 = *(const float4*)(xb + (size_t)p0.x * FEAT);
        float4 v1 = *(const float4*)(xb + (size_t)p1.x * FEAT);
        float4 v2 = *(const float4*)(xb + (size_t)p2.x * FEAT);
        float4 v3 = *(const float4*)(xb + (size_t)p3.x * FEAT);
        float w0 = __int_as_float(p0.y), w1 = __int_as_float(p1.y);
        float w2 = __int_as_float(p2.y), w3 = __int_as_float(p3.y);
        ax += w0 * v0.x; ay += w0 * v0.y; az += w0 * v0.z; aw += w0 * v0.w;
        ax += w1 * v1.x; ay += w1 * v1.y; az += w1 * v1.z; aw += w1 * v1.w;
        ax += w2 * v2.x; ay += w2 * v2.y; az += w2 * v2.z; aw += w2 * v2.w;
        ax += w3 * v3.x; ay += w3 * v3.y; az += w3 * v3.z; aw += w3 * v3.w;
    }
    for (; j < end; j++) {
        int2 p0 = g_sorted[j];
        float4 v0 = *(const float4*)(xb + (size_t)p0.x * FEAT);
        float w0 = __int_as_float(p0.y);
        ax += w0 * v0.x; ay += w0 * v0.y; az += w0 * v0.z; aw += w0 * v0.w;
    }

    const float inv = g_inv[dst];
    float4 r = make_float4(ax * inv, ay * inv, az * inv, aw * inv);
    float* o = out + (size_t)b * (DST_SIZE * FEAT) + (size_t)dst * FEAT + fg * 4;
    *(float4*)o = r;
}

// ---------------------------------------------------------------------------
// kernel_launch
// ---------------------------------------------------------------------------
extern "C" void kernel_launch(void* const* d_in, const int* in_sizes, int n_in,
                              void* d_out, int out_size) {
    const float* x       = (const float*)d_in[0];
    const float* weights = (const float*)d_in[1];
    const int*   src_idx = (const int*)d_in[2];
    const int*   dst_idx = (const int*)d_in[3];
    float*       out     = (float*)d_out;
    const int n_edges = in_sizes[1];

    k_zero<<<(DST_SIZE + 255) / 256, 256>>>();
    k_hist<<<(n_edges + 255) / 256, 256>>>(weights, dst_idx, n_edges);
    k_scan_a<<<SCAN_BLOCKS, SCAN_CHUNK>>>();
    k_scan_c<<<SCAN_BLOCKS, SCAN_CHUNK>>>();
    k_scatter<<<(n_edges + 255) / 256, 256>>>(weights, src_idx, dst_idx, n_edges);
    k_reduce<<<DST_SIZE / 8, 256>>>(x, out);
}